// round 17
// baseline (speedup 1.0000x reference)
#include <cuda_runtime.h>
#include <math.h>

#define T_LEN 32
#define KP    2048
#define CPB   16                       // columns per CTA
#define GPC   16                       // threads per column
#define BLOCK 256
#define GRID  128                      // best measured PDL shape
#define HALF  (KP / 2)

// sp = sqrt(1/32); 0.5/sp^2 = 16 exactly
#define LOG_SP     (-1.7328679513998633f)
#define HALF_L2PI  (0.9189385332046727f)
#define LOG_K      (7.6246189861593985f)
#define C2EXP      (-23.083120654223414f)   // -16 * log2(e)
#define L2E        (1.4426950408889634f)
#define F_INF      (__int_as_float(0x7f800000))

__device__ float g_zs[T_LEN * KP];
__device__ float g_cA[T_LEN * KP];    // (A - LOG_K) * log2e, pre-folded
__device__ float g_w [T_LEN][KP];     // w_t[j] = C2*z_{t,j}^2 + r_t[j]*log2e

__device__ __forceinline__ float ex2(float t) {
    float r; asm("ex2.approx.ftz.f32 %0,%1;" : "=f"(r) : "f"(t)); return r;
}
__device__ __forceinline__ float lg2(float t) {
    float r; asm("lg2.approx.f32 %0,%1;" : "=f"(r) : "f"(t)); return r;
}

// Setup: z = mu + std*eps; A = 0.5*eps^2 + ls - LOG_SP; cA = (A - LOG_K)*log2e;
//        w0 = (A - 32 z^2) * log2e
__global__ void __launch_bounds__(256) setup_kernel(const float* __restrict__ means,
                                                    const float* __restrict__ log_stds,
                                                    const float* __restrict__ eps) {
    int idx = blockIdx.x * 256 + threadIdx.x;      // grid covers T_LEN*KP exactly
    int t = idx >> 11;
    int k = idx & (KP - 1);
    float ls = log_stds[t];
    float mu = means[t];
    float e  = eps[idx];
    float sg = ex2(ls * L2E);                      // std = exp(log_std)
    float z  = fmaf(sg, e, mu);
    float A  = fmaf(0.5f * e, e, ls) - LOG_SP;
    g_zs[idx] = z;
    g_cA[idx] = (A - LOG_K) * L2E;
    if (t == 0)
        g_w[0][k] = fmaf(-32.0f * z, z, A) * L2E;
}

// One scan step (PDL). Post-sync path: pipelined w ingest (overlap LDG-B with compute-A).
__global__ void __launch_bounds__(BLOCK) step_kernel(int t) {
    __shared__ __align__(16) float az[KP];   // z_{t-1,j}
    __shared__ __align__(16) float sw[KP];   // w_{t-1,j}

    const int tid = threadIdx.x;
    const int c   = tid >> 4;                 // column-in-block 0..15
    const int g   = tid & (GPC - 1);
    const int k   = blockIdx.x * CPB + c;     // always < KP

    cudaTriggerProgrammaticLaunchCompletion();     // successor may launch now

    // ---- pre-sync prologue: setup-owned data only ----
    const float4* __restrict__ z4 = reinterpret_cast<const float4*>(g_zs + (t - 1) * KP);
    #pragma unroll
    for (int s = 0; s < 2; s++) {
        int f = tid + s * BLOCK;
        reinterpret_cast<float4*>(az)[f] = z4[f];
    }
    const float zk  = g_zs[t * KP + k];
    const float cak = g_cA[t * KP + k];
    const float qk  = C2EXP * zk * zk;
    const float m2  = -2.0f * C2EXP * zk;
    const float ck  = cak + qk;                    // w_out = ck + lg2(S)

    cudaGridDependencySynchronize();               // wait for w_{t-1}

    // ---- phase A: load + stage first half of w ----
    const float4* __restrict__ w4 = reinterpret_cast<const float4*>(g_w[t - 1]);
    float4 wa = w4[tid];                           // j in [0, 1024)
    reinterpret_cast<float4*>(sw)[tid] = wa;
    __syncthreads();                               // half A + az visible

    // issue half-B load; its latency hides under compute-A
    float4 wb = w4[tid + 256];                     // j in [1024, 2048)

    // ---- compute half A ----
    const float2* __restrict__ az2 = reinterpret_cast<const float2*>(az);
    const float2* __restrict__ w2  = reinterpret_cast<const float2*>(sw);
    float S0 = 0.0f, S1 = 0.0f;
    #pragma unroll 8
    for (int i = 0; i < HALF / (2 * GPC); i++) {   // 32 iters over j in [0,1024)
        int f = i * GPC + g;                       // half-warps mirror -> LDS broadcast
        float2 a = az2[f];
        float2 v = w2[f];
        S0 += ex2(fmaf(m2, a.x, v.x) + qk);
        S1 += ex2(fmaf(m2, a.y, v.y) + qk);
    }

    // ---- stage half B, then compute it ----
    reinterpret_cast<float4*>(sw)[tid + 256] = wb;
    __syncthreads();
    #pragma unroll 8
    for (int i = HALF / (2 * GPC); i < KP / (2 * GPC); i++) {  // j in [1024,2048)
        int f = i * GPC + g;
        float2 a = az2[f];
        float2 v = w2[f];
        S0 += ex2(fmaf(m2, a.x, v.x) + qk);
        S1 += ex2(fmaf(m2, a.y, v.y) + qk);
    }
    float S = S0 + S1;
    #pragma unroll
    for (int s = GPC / 2; s; s >>= 1)
        S += __shfl_xor_sync(0xffffffffu, S, s, GPC);

    if (g == 0)
        g_w[t][k] = ck + lg2(fmaxf(S, 1e-37f));
}

// Final: out = log( sum_j exp(r_j + L_j) ) - logK, unshifted in 2^-domain.
__global__ void __launch_bounds__(256) final_kernel(float* __restrict__ out) {
    __shared__ __align__(16) float sb[KP];   // -C2*z^2 + L*log2e  (pre-sync)
    __shared__ float red[8];
    const int tid  = threadIdx.x;
    const int wid  = tid >> 5;
    const int lane = tid & 31;

    cudaTriggerProgrammaticLaunchCompletion();

    const float* __restrict__ zrow = g_zs + (T_LEN - 1) * KP;
    #pragma unroll
    for (int i = 0; i < KP / 256; i++) {
        int j = tid + i * 256;
        float z  = zrow[j];
        float dd = 0.5f - z;
        float Lv = fmaf(-0.5f * dd, dd, -HALF_L2PI);   // logN(0.5; z, 1)
        sb[j] = fmaf(Lv, L2E, -C2EXP * z * z);
    }

    cudaGridDependencySynchronize();

    const float* __restrict__ win = g_w[T_LEN - 1];
    float S = 0.0f;
    #pragma unroll
    for (int i = 0; i < KP / 256; i++) {
        int j = tid + i * 256;
        S += ex2(win[j] + sb[j]);
    }
    #pragma unroll
    for (int m = 16; m; m >>= 1)
        S += __shfl_xor_sync(0xffffffffu, S, m);
    if (lane == 0) red[wid] = S;
    __syncthreads();
    if (tid == 0) {
        float tot = 0.0f;
        #pragma unroll
        for (int w = 0; w < 8; w++) tot += red[w];
        out[0] = logf(tot) - LOG_K;
    }
}

extern "C" void kernel_launch(void* const* d_in, const int* in_sizes, int n_in,
                              void* d_out, int out_size) {
    const float* means    = (const float*)d_in[0];
    const float* log_stds = (const float*)d_in[1];
    const float* eps      = (const float*)d_in[2];
    float* out = (float*)d_out;

    setup_kernel<<<(T_LEN * KP) / 256, 256>>>(means, log_stds, eps);

    cudaLaunchAttribute attr[1];
    attr[0].id = cudaLaunchAttributeProgrammaticStreamSerialization;
    attr[0].val.programmaticStreamSerializationAllowed = 1;

    cudaLaunchConfig_t cfg = {};
    cfg.gridDim  = dim3(GRID, 1, 1);
    cfg.blockDim = dim3(BLOCK, 1, 1);
    cfg.dynamicSmemBytes = 0;
    cfg.stream = 0;
    cfg.attrs = attr;
    cfg.numAttrs = 1;

    for (int t = 1; t < T_LEN; t++)
        cudaLaunchKernelEx(&cfg, step_kernel, t);

    cudaLaunchConfig_t cfgf = cfg;
    cfgf.gridDim  = dim3(1, 1, 1);
    cfgf.blockDim = dim3(256, 1, 1);
    cudaLaunchKernelEx(&cfgf, final_kernel, out);
}